// round 13
// baseline (speedup 1.0000x reference)
#include <cuda_runtime.h>
#include <cuda_fp16.h>
#include <cstdint>

#define C_DIM   64
#define TILE_P  128
#define TILES   4
#define STRIDE  132                       // floats per c-row (528B): conflict-free
#define BUF_FLOATS (C_DIM * STRIDE)       // 8448 floats = 33792 B per buffer
#define SMEM_BYTES (2 * BUF_FLOATS * 4)   // 67584 B
#define TILE_BYTES (TILE_P * C_DIM * 4)   // 32768 B of payload per tile

// M fragments (fp16 pairs) pre-packed in per-lane mma order:
// index ((gblk*4+k)*4+j)*32+lane
__device__ uint32_t g_Ah[4 * 4 * 4 * 32];

__device__ __forceinline__ uint32_t pack_f16(float lo, float hi) {
    uint32_t r;
    asm("cvt.rn.f16x2.f32 %0, %1, %2;" : "=r"(r) : "f"(hi), "f"(lo));
    return r;
}

#define MMA(d, A, b0, b1)                                                     \
    asm volatile("mma.sync.aligned.m16n8k16.row.col.f32.f16.f16.f32 "         \
                 "{%0,%1,%2,%3}, {%4,%5,%6,%7}, {%8,%9}, {%0,%1,%2,%3};"      \
                 : "+f"((d)[0]), "+f"((d)[1]), "+f"((d)[2]), "+f"((d)[3])     \
                 : "r"((A)[0]), "r"((A)[1]), "r"((A)[2]), "r"((A)[3]),        \
                   "r"(b0), "r"(b1))

// ---------------------------------------------------------------------------
// Kernel A: M = Qinv * diag(exp(T*(-2*|S|))) * Q, emitted directly as fp16
// mma A-fragments. grid 8 x 256; thread t computes M[g][c], M[g][c+1].
// ---------------------------------------------------------------------------
__global__ void build_M_kernel(const float* __restrict__ S,
                               const float* __restrict__ Q,
                               const float* __restrict__ Qinv,
                               const int* __restrict__ T) {
    __shared__ float sQ[C_DIM * C_DIM];
    __shared__ float sQi[C_DIM * C_DIM];
    __shared__ float se[C_DIM];
    int tid = threadIdx.x;
    for (int i = tid; i < C_DIM * C_DIM; i += blockDim.x) {
        sQ[i]  = Q[i];
        sQi[i] = Qinv[i];
    }
    if (tid < C_DIM) {
        float t_total = (float)(*T);
        se[tid] = expf(t_total * (-2.0f * fabsf(S[tid])));
    }
    __syncthreads();

    int t = blockIdx.x * blockDim.x + tid;   // 0..2047
    int g = t >> 5;
    int c = (t & 31) * 2;
    float a0 = 0.0f, a1 = 0.0f;
    #pragma unroll
    for (int f = 0; f < C_DIM; f++) {
        float w = sQi[g * C_DIM + f] * se[f];
        a0 += w * sQ[f * C_DIM + c];
        a1 += w * sQ[f * C_DIM + c + 1];
    }
    uint32_t h = pack_f16(a0, a1);

    int gblk = g >> 4;
    int gg   = g & 15;
    int gid  = gg & 7;
    int half = gg >> 3;
    int k    = c >> 4;
    int cc   = c & 15;
    int tig  = (cc >> 1) & 3;
    int j    = ((cc >> 3) << 1) + half;
    int lane = gid * 4 + tig;
    int off  = (((gblk * 4) + k) * 4 + j) * 32 + lane;
    g_Ah[off] = h;
}

// ---------------------------------------------------------------------------
// Kernel B: 256 thr, 4 tiles of 128 px. Warp = (gpair: 32 g) x (pq: 32 px).
// Raw f32 x tiles stream via cp.async.bulk (UBLKCP, DMA-engine) into a
// double buffer with PER-BUFFER mbarrier completion: waiting on tile t does
// not interact with tile t+1's in-flight transfer. Consumers do
// conflict-free LDS.32 and split to fp16 hi/lo in registers.
// D = Mh*(Xh + Xl): 4 MMAs per (k,nt). 3 CTAs/SM.
// ---------------------------------------------------------------------------
__global__ __launch_bounds__(256, 3)
void apply_mma_kernel(const float* __restrict__ x,
                      float* __restrict__ out, int HW) {
    extern __shared__ __align__(16) float sRaw[];   // 2 x [64][STRIDE]
    __shared__ __align__(8) unsigned long long mbar[2];

    int tid   = threadIdx.x;
    int wid   = tid >> 5;
    int lane  = tid & 31;
    int gid   = lane >> 2;
    int tig   = lane & 3;
    int gpair = wid & 1;        // g half (32 rows)
    int pq    = wid >> 1;       // pixel quarter (32 px)

    // ---- A fragments: 2 quadrants x 4 k x 4 j, fp16 hi only (32 regs) ----
    uint32_t Ah[2][4][4];
    #pragma unroll
    for (int q = 0; q < 2; q++)
        #pragma unroll
        for (int k = 0; k < 4; k++)
            #pragma unroll
            for (int j = 0; j < 4; j++) {
                int off = (((gpair * 2 + q) * 4 + k) * 4 + j) * 32 + lane;
                Ah[q][k][j] = g_Ah[off];
            }

    // ---- CTA coords: 512 consecutive pixels (never crosses batch) ----
    int Q0 = blockIdx.x * (TILE_P * TILES);
    int b  = Q0 / HW;
    int p0 = Q0 - b * HW;
    const float* xb = x   + (size_t)b * C_DIM * HW + p0;
    float*       ob = out + (size_t)b * C_DIM * HW + p0;

    uint32_t sb = (uint32_t)__cvta_generic_to_shared(sRaw);
    uint32_t mb0 = (uint32_t)__cvta_generic_to_shared(&mbar[0]);

    if (tid == 0) {
        asm volatile("mbarrier.init.shared.b64 [%0], 1;" :: "r"(mb0) : "memory");
        asm volatile("mbarrier.init.shared.b64 [%0], 1;" :: "r"(mb0 + 8) : "memory");
    }
    __syncthreads();

    // issue whole tile t into buffer t&1 via 64 bulk row copies (tid 0 only)
    #define ISSUE_TILE(t)                                                      \
        do {                                                                   \
            uint32_t mbt = mb0 + ((t) & 1) * 8;                                \
            asm volatile("mbarrier.arrive.expect_tx.shared.b64 _, [%0], %1;"   \
                         :: "r"(mbt), "r"((uint32_t)TILE_BYTES) : "memory");   \
            uint32_t sbase = sb + (((t) & 1) * BUF_FLOATS) * 4;                \
            const float* gbase = xb + (t) * TILE_P;                            \
            _Pragma("unroll 4")                                                \
            for (int row = 0; row < C_DIM; row++) {                            \
                asm volatile(                                                  \
                    "cp.async.bulk.shared::cluster.global"                     \
                    ".mbarrier::complete_tx::bytes [%0], [%1], %2, [%3];"      \
                    :: "r"(sbase + (uint32_t)(row * STRIDE) * 4),              \
                       "l"(gbase + (size_t)row * HW),                          \
                       "r"((uint32_t)(TILE_P * 4)), "r"(mbt) : "memory");      \
            }                                                                  \
        } while (0)

    if (tid == 0) ISSUE_TILE(0);

    float d[2][4][4];
    #pragma unroll
    for (int q = 0; q < 2; q++)
        #pragma unroll
        for (int nt = 0; nt < 4; nt++)
            #pragma unroll
            for (int j = 0; j < 4; j++) d[q][nt][j] = 0.0f;

    #pragma unroll 1
    for (int t = 0; t < TILES; t++) {
        // wait tile t ready (per-buffer parity: buffer t&1, fill #(t>>1))
        {
            uint32_t mbt = mb0 + (t & 1) * 8;
            uint32_t par = (uint32_t)((t >> 1) & 1);
            uint32_t done;
            do {
                asm volatile(
                    "{\n\t.reg .pred p;\n\t"
                    "mbarrier.try_wait.parity.acquire.cta.shared::cta.b64 p, [%1], %2, 0x989680;\n\t"
                    "selp.b32 %0, 1, 0, p;\n\t}"
                    : "=r"(done) : "r"(mbt), "r"(par) : "memory");
            } while (!done);
        }
        // overlap: start streaming tile t+1 while computing tile t
        if (tid == 0 && t + 1 < TILES) ISSUE_TILE(t + 1);

        const float* sf = sRaw + (t & 1) * BUF_FLOATS;
        #pragma unroll
        for (int k = 0; k < 4; k++) {
            #pragma unroll
            for (int nt = 0; nt < 4; nt++) {
                int p  = pq * 32 + nt * 8 + gid;
                int c0 = k * 16 + tig * 2;
                float f0 = sf[(c0)     * STRIDE + p];
                float f1 = sf[(c0 + 1) * STRIDE + p];
                float f2 = sf[(c0 + 8) * STRIDE + p];
                float f3 = sf[(c0 + 9) * STRIDE + p];
                uint32_t h0 = pack_f16(f0, f1);
                uint32_t h1 = pack_f16(f2, f3);
                float2 b0 = __half22float2(*(__half2*)&h0);
                float2 b1 = __half22float2(*(__half2*)&h1);
                uint32_t l0 = pack_f16(f0 - b0.x, f1 - b0.y);
                uint32_t l1 = pack_f16(f2 - b1.x, f3 - b1.y);
                MMA(d[0][nt], Ah[0][k], h0, h1);
                MMA(d[0][nt], Ah[0][k], l0, l1);
                MMA(d[1][nt], Ah[1][k], h0, h1);
                MMA(d[1][nt], Ah[1][k], l0, l1);
            }
        }

        // ---- epilogue tile t: coalesced float2 stores, reset acc ----
        #pragma unroll
        for (int q = 0; q < 2; q++) {
            int r0 = gpair * 32 + q * 16 + gid;
            float* o0 = ob + (size_t)r0 * HW + t * TILE_P + pq * 32;
            float* o1 = o0 + (size_t)8 * HW;
            #pragma unroll
            for (int nt = 0; nt < 4; nt++) {
                int p = nt * 8 + tig * 2;
                float2 v0; v0.x = d[q][nt][0]; v0.y = d[q][nt][1];
                float2 v1; v1.x = d[q][nt][2]; v1.y = d[q][nt][3];
                *(float2*)(o0 + p) = v0;
                *(float2*)(o1 + p) = v1;
                d[q][nt][0] = 0.0f; d[q][nt][1] = 0.0f;
                d[q][nt][2] = 0.0f; d[q][nt][3] = 0.0f;
            }
        }
        // all consumers done with buffer t&1 before it is refilled at t+2
        __syncthreads();
    }
}

// ---------------------------------------------------------------------------
// Inputs: x [4,64,512,512] f32, S [64] f32, Q [64,64] f32, Qinv [64,64] f32,
// T [] int32. Output: f32 same shape as x.
// ---------------------------------------------------------------------------
extern "C" void kernel_launch(void* const* d_in, const int* in_sizes, int n_in,
                              void* d_out, int out_size) {
    const float* x   = (const float*)d_in[0];
    const float* S   = (const float*)d_in[1];
    const float* Q   = (const float*)d_in[2];
    const float* Qi  = (const float*)d_in[3];
    const int*   T   = (const int*)d_in[4];
    float*       out = (float*)d_out;

    int Npix = in_sizes[0] / C_DIM;   // B*H*W = 1,048,576
    int HW   = Npix / 4;              // B = 4

    cudaFuncSetAttribute(apply_mma_kernel,
                         cudaFuncAttributeMaxDynamicSharedMemorySize, SMEM_BYTES);

    build_M_kernel<<<8, 256>>>(S, Q, Qi, T);
    int grid = Npix / (TILE_P * TILES);   // 2048
    apply_mma_kernel<<<grid, 256, SMEM_BYTES>>>(x, out, HW);
}

// round 14
// speedup vs baseline: 1.0279x; 1.0279x over previous
#include <cuda_runtime.h>
#include <cuda_fp16.h>
#include <cstdint>

#define C_DIM   64
#define TILE_P  64
#define TILES   4
#define STRIDE  68                        // floats per c-row (272B): 68%16==4 -> conflict-free
#define BUF_FLOATS (C_DIM * STRIDE)       // 4352 floats = 17408 B per buffer
#define SMEM_BYTES (2 * BUF_FLOATS * 4)   // 34816 B

// M fragments (fp16 pairs) pre-packed in per-lane mma order:
// index ((gblk*4+k)*4+j)*32+lane
__device__ uint32_t g_Ah[4 * 4 * 4 * 32];

__device__ __forceinline__ uint32_t pack_f16(float lo, float hi) {
    uint32_t r;
    asm("cvt.rn.f16x2.f32 %0, %1, %2;" : "=r"(r) : "f"(hi), "f"(lo));
    return r;
}

#define MMA(d, A, b0, b1)                                                     \
    asm volatile("mma.sync.aligned.m16n8k16.row.col.f32.f16.f16.f32 "         \
                 "{%0,%1,%2,%3}, {%4,%5,%6,%7}, {%8,%9}, {%0,%1,%2,%3};"      \
                 : "+f"((d)[0]), "+f"((d)[1]), "+f"((d)[2]), "+f"((d)[3])     \
                 : "r"((A)[0]), "r"((A)[1]), "r"((A)[2]), "r"((A)[3]),        \
                   "r"(b0), "r"(b1))

#define CP_ASYNC16(sa, ga) \
    asm volatile("cp.async.cg.shared.global [%0], [%1], 16;" :: "r"(sa), "l"(ga))

// ---------------------------------------------------------------------------
// Kernel A: M = Qinv * diag(exp(T*(-2*|S|))) * Q, emitted directly as fp16
// mma A-fragments. grid 8 x 256; thread t computes M[g][c], M[g][c+1].
// ---------------------------------------------------------------------------
__global__ void build_M_kernel(const float* __restrict__ S,
                               const float* __restrict__ Q,
                               const float* __restrict__ Qinv,
                               const int* __restrict__ T) {
    __shared__ float sQ[C_DIM * C_DIM];
    __shared__ float sQi[C_DIM * C_DIM];
    __shared__ float se[C_DIM];
    int tid = threadIdx.x;
    for (int i = tid; i < C_DIM * C_DIM; i += blockDim.x) {
        sQ[i]  = Q[i];
        sQi[i] = Qinv[i];
    }
    if (tid < C_DIM) {
        float t_total = (float)(*T);
        se[tid] = expf(t_total * (-2.0f * fabsf(S[tid])));
    }
    __syncthreads();

    int t = blockIdx.x * blockDim.x + tid;   // 0..2047
    int g = t >> 5;
    int c = (t & 31) * 2;
    float a0 = 0.0f, a1 = 0.0f;
    #pragma unroll
    for (int f = 0; f < C_DIM; f++) {
        float w = sQi[g * C_DIM + f] * se[f];
        a0 += w * sQ[f * C_DIM + c];
        a1 += w * sQ[f * C_DIM + c + 1];
    }
    uint32_t h = pack_f16(a0, a1);

    int gblk = g >> 4;
    int gg   = g & 15;
    int gid  = gg & 7;
    int half = gg >> 3;
    int k    = c >> 4;
    int cc   = c & 15;
    int tig  = (cc >> 1) & 3;
    int j    = ((cc >> 3) << 1) + half;
    int lane = gid * 4 + tig;
    int off  = (((gblk * 4) + k) * 4 + j) * 32 + lane;
    g_Ah[off] = h;
}

// ---------------------------------------------------------------------------
// Kernel B: 256 thr, 4 tiles of 64 px. Warp = (gpair: 32 g) x (pq: 16 px).
// 16 accumulator regs + 32 A regs -> ~64 regs -> 4 CTAs/SM (47% occ).
// R12 schedule: wait 0 -> sync -> issue next -> compute. Consumers do
// conflict-free LDS.32 and split to fp16 hi/lo; D = Mh*(Xh+Xl).
// ---------------------------------------------------------------------------
__global__ __launch_bounds__(256, 4)
void apply_mma_kernel(const float* __restrict__ x,
                      float* __restrict__ out, int HW) {
    extern __shared__ __align__(16) float sRaw[];   // 2 x [64][STRIDE]

    int tid   = threadIdx.x;
    int wid   = tid >> 5;
    int lane  = tid & 31;
    int gid   = lane >> 2;
    int tig   = lane & 3;
    int gpair = wid & 1;        // g half (32 rows)
    int pq    = wid >> 1;       // pixel sixteenth-quarter (16 px)

    // ---- A fragments: 2 quadrants x 4 k x 4 j, fp16 hi only (32 regs) ----
    uint32_t Ah[2][4][4];
    #pragma unroll
    for (int q = 0; q < 2; q++)
        #pragma unroll
        for (int k = 0; k < 4; k++)
            #pragma unroll
            for (int j = 0; j < 4; j++) {
                int off = (((gpair * 2 + q) * 4 + k) * 4 + j) * 32 + lane;
                Ah[q][k][j] = g_Ah[off];
            }

    // ---- CTA coords: 256 consecutive pixels (never crosses batch) ----
    int Q0 = blockIdx.x * (TILE_P * TILES);
    int b  = Q0 / HW;
    int p0 = Q0 - b * HW;
    const float* xb = x   + (size_t)b * C_DIM * HW + p0;
    float*       ob = out + (size_t)b * C_DIM * HW + p0;

    uint32_t sb = (uint32_t)__cvta_generic_to_shared(sRaw);
    int prow = tid >> 4;            // producer row base 0..15
    int pcol = (tid & 15) * 4;      // float col (16B segment)

    // issue whole tile t into buffer t&1 (4 x 16B per thread, 1 commit)
    #define ISSUE_TILE(t)                                                      \
        do {                                                                   \
            uint32_t sbase = sb + (((t) & 1) * BUF_FLOATS) * 4;                \
            const float* gbase = xb + (t) * TILE_P + pcol;                     \
            _Pragma("unroll")                                                  \
            for (int i = 0; i < 4; i++) {                                      \
                int row = i * 16 + prow;                                       \
                CP_ASYNC16(sbase + (uint32_t)(row * STRIDE + pcol) * 4,        \
                           gbase + (size_t)row * HW);                          \
            }                                                                  \
            asm volatile("cp.async.commit_group;" ::: "memory");               \
        } while (0)

    ISSUE_TILE(0);

    float d[2][2][4];
    #pragma unroll
    for (int q = 0; q < 2; q++)
        #pragma unroll
        for (int nt = 0; nt < 2; nt++)
            #pragma unroll
            for (int j = 0; j < 4; j++) d[q][nt][j] = 0.0f;

    #pragma unroll 1
    for (int t = 0; t < TILES; t++) {
        asm volatile("cp.async.wait_group 0;" ::: "memory");
        __syncthreads();
        if (t + 1 < TILES) ISSUE_TILE(t + 1);

        const float* sf = sRaw + (t & 1) * BUF_FLOATS;
        #pragma unroll
        for (int k = 0; k < 4; k++) {
            #pragma unroll
            for (int nt = 0; nt < 2; nt++) {
                int p  = pq * 16 + nt * 8 + gid;
                int c0 = k * 16 + tig * 2;
                float f0 = sf[(c0)     * STRIDE + p];
                float f1 = sf[(c0 + 1) * STRIDE + p];
                float f2 = sf[(c0 + 8) * STRIDE + p];
                float f3 = sf[(c0 + 9) * STRIDE + p];
                uint32_t h0 = pack_f16(f0, f1);
                uint32_t h1 = pack_f16(f2, f3);
                float2 b0 = __half22float2(*(__half2*)&h0);
                float2 b1 = __half22float2(*(__half2*)&h1);
                uint32_t l0 = pack_f16(f0 - b0.x, f1 - b0.y);
                uint32_t l1 = pack_f16(f2 - b1.x, f3 - b1.y);
                MMA(d[0][nt], Ah[0][k], h0, h1);
                MMA(d[0][nt], Ah[0][k], l0, l1);
                MMA(d[1][nt], Ah[1][k], h0, h1);
                MMA(d[1][nt], Ah[1][k], l0, l1);
            }
        }

        // ---- epilogue tile t: coalesced float2 stores, reset acc ----
        #pragma unroll
        for (int q = 0; q < 2; q++) {
            int r0 = gpair * 32 + q * 16 + gid;
            float* o0 = ob + (size_t)r0 * HW + t * TILE_P + pq * 16;
            float* o1 = o0 + (size_t)8 * HW;
            #pragma unroll
            for (int nt = 0; nt < 2; nt++) {
                int p = nt * 8 + tig * 2;
                float2 v0; v0.x = d[q][nt][0]; v0.y = d[q][nt][1];
                float2 v1; v1.x = d[q][nt][2]; v1.y = d[q][nt][3];
                *(float2*)(o0 + p) = v0;
                *(float2*)(o1 + p) = v1;
                d[q][nt][0] = 0.0f; d[q][nt][1] = 0.0f;
                d[q][nt][2] = 0.0f; d[q][nt][3] = 0.0f;
            }
        }
    }
}

// ---------------------------------------------------------------------------
// Inputs: x [4,64,512,512] f32, S [64] f32, Q [64,64] f32, Qinv [64,64] f32,
// T [] int32. Output: f32 same shape as x.
// ---------------------------------------------------------------------------
extern "C" void kernel_launch(void* const* d_in, const int* in_sizes, int n_in,
                              void* d_out, int out_size) {
    const float* x   = (const float*)d_in[0];
    const float* S   = (const float*)d_in[1];
    const float* Q   = (const float*)d_in[2];
    const float* Qi  = (const float*)d_in[3];
    const int*   T   = (const int*)d_in[4];
    float*       out = (float*)d_out;

    int Npix = in_sizes[0] / C_DIM;   // B*H*W = 1,048,576
    int HW   = Npix / 4;              // B = 4

    cudaFuncSetAttribute(apply_mma_kernel,
                         cudaFuncAttributeMaxDynamicSharedMemorySize, SMEM_BYTES);

    build_M_kernel<<<8, 256>>>(S, Q, Qi, T);
    int grid = Npix / (TILE_P * TILES);   // 4096
    apply_mma_kernel<<<grid, 256, SMEM_BYTES>>>(x, out, HW);
}